// round 15
// baseline (speedup 1.0000x reference)
#include <cuda_runtime.h>
#include <cuda_fp16.h>
#include <cstdint>

#define GD 160
#define GH 160
#define GW 160
#define CIN 32
#define COUT 64
#define NK 27
#define TILE_V 128
#define NMAX 400000

#if defined(__CUDA_ARCH_FEAT_SM103_ALL) || defined(__CUDA_ARCH_FEAT_SM100_ALL) || defined(__CUDA_ARCH_FEAT_SM101_ALL)
#define HAS_TCGEN05 1
#else
#define HAS_TCGEN05 0
#endif

// ---------------- device scratch ----------------
__device__ int      g_grid[GD * GH * GW];        // voxel -> row index
__device__ __half   g_packF[NMAX * CIN];         // fp16 features (64B per voxel row)
__device__ __half   g_Bw[NK * 4096];             // 27 x 8KB pre-swizzled fp16 B tiles

// ---------------- helpers ----------------
__device__ __forceinline__ uint32_t smem_u32(const void* p) {
    uint32_t a;
    asm("{ .reg .u64 t; cvta.to.shared.u64 t, %1; cvt.u32.u64 %0, t; }" : "=r"(a) : "l"(p));
    return a;
}

__host__ __device__ __forceinline__ uint32_t swz128(uint32_t off) {
    return off ^ ((off >> 3) & 0x70);
}

// SMEM descriptor: SW128, version=1, SBO=64 (1024B), LBO=1 (16B)
__device__ __forceinline__ uint64_t make_desc(uint32_t addr) {
    const uint64_t base =
        (uint64_t(2) << 61) | (uint64_t(1) << 46) | (uint64_t(64) << 32) | (uint64_t(1) << 16);
    return base | ((uint64_t)(addr >> 4) & 0x3FFF);
}

// idesc kind::f16: accum F32 (bit4), A=F16, B=F16, N=64 (8<<17), M=128 (8<<24)
#define MMA_IDESC 0x8100010u

#if HAS_TCGEN05
// TS-mode: A in TMEM ([a_tmem]), B via smem descriptor.
__device__ __forceinline__ void mma_f16_ts(uint32_t d_tmem, uint32_t a_tmem,
                                           uint64_t b_desc, uint32_t en) {
    asm volatile(
        "{\n\t"
        ".reg .pred p;\n\t"
        "setp.ne.u32 p, %4, 0;\n\t"
        "tcgen05.mma.cta_group::1.kind::f16 [%0], [%1], %2, %3, {%5, %5, %5, %5}, p;\n\t"
        "}"
        :: "r"(d_tmem), "r"(a_tmem), "l"(b_desc), "r"(MMA_IDESC), "r"(en), "r"(0u)
        : "memory");
}
#endif

#define MBARRIER_WAIT_PARITY(mbar, parity) do {                                   \
    uint32_t _m = (mbar); uint32_t _p = (parity); uint32_t _done;                  \
    asm volatile(                                                                  \
        "{\n\t.reg .pred p;\n\t"                                                   \
        "mbarrier.try_wait.parity.acquire.cta.shared::cta.b64 p, [%1], %2;\n\t"    \
        "selp.b32 %0, 1, 0, p;\n\t}"                                               \
        : "=r"(_done) : "r"(_m), "r"(_p) : "memory");                              \
    if (!_done) {                                                                  \
        asm volatile(                                                              \
            "{\n\t.reg .pred P1;\n\t"                                              \
            "WL_%=:\n\t"                                                           \
            "mbarrier.try_wait.parity.acquire.cta.shared::cta.b64 P1, [%0], %1, 0x989680;\n\t" \
            "@P1 bra.uni WD_%=;\n\t"                                               \
            "bra.uni WL_%=;\n\t"                                                   \
            "WD_%=:\n\t}"                                                          \
            :: "r"(_m), "r"(_p) : "memory");                                       \
    }                                                                              \
} while (0)

// ---------------- prep kernels ----------------
__global__ void init_grid_kernel() {
    int i = blockIdx.x * blockDim.x + threadIdx.x;
    int4* p = reinterpret_cast<int4*>(g_grid);
    const int total = (GD * GH * GW) / 4;
    if (i < total) p[i] = make_int4(-1, -1, -1, -1);
}

// Fused: pack features (fp16) + scatter + pack weights (fp16, pre-swizzled).
__global__ void prep_kernel(const int* __restrict__ coors,
                            const float* __restrict__ feat,
                            const float* __restrict__ weight,
                            int n) {
    int i = blockIdx.x * blockDim.x + threadIdx.x;
    const int nF = n * CIN;
    if (i < nF) {
        g_packF[i] = __float2half(feat[i]);
        return;
    }
    i -= nF;
    if (i < n) {
        int z = coors[4 * i + 1];
        int y = coors[4 * i + 2];
        int x = coors[4 * i + 3];
        g_grid[(z * GH + y) * GW + x] = i;
        return;
    }
    i -= n;
    if (i < NK * COUT * CIN) {
        int k  = i / (COUT * CIN);
        int rr = i % (COUT * CIN);
        int nn = rr / CIN;   // cout (B row)
        int c  = rr % CIN;   // cin
        float w = weight[k * CIN * COUT + c * COUT + nn];
        uint32_t sw = swz128((uint32_t)(nn * 128 + c * 2));
        g_Bw[k * 4096 + (sw >> 1)] = __float2half(w);
    }
}

// ---------------- main tensor-core kernel ----------------
// A operand lives in TMEM (TS-mode MMA): gather LDG -> registers -> tcgen05.st.
// No A smem, no STS pass through L1, no async-proxy fence.
// TMEM layout per CTA (128 cols): A0 cols 0-15, A1 cols 16-31, D cols 64-127.
// Thread wg_tid owns row wg_tid; warpgroup 0 = K cols 0-7, warpgroup 1 = 8-15.
// Distance-2 pipeline for gather LDG and grid lookup (R14 winner) preserved.
// Dyn smem: B0[8K] B1[8K] only.
__global__ __launch_bounds__(256) void conv_tc_kernel(
    const int*   __restrict__ coors,
    const float* __restrict__ bias,
    float*       __restrict__ out,
    int n)
{
#if HAS_TCGEN05
    extern __shared__ uint32_t dynsmem[];
    __shared__ int   sIdx[2][TILE_V];
    __shared__ int   sZ[TILE_V], sY[TILE_V], sX[TILE_V];
    __shared__ float sBias[COUT];
    __shared__ uint32_t sTmem;
    __shared__ __align__(8) uint64_t sMbarMMA[2];
    __shared__ __align__(8) uint64_t sMbarTMA[2];

    const int tid    = threadIdx.x;
    const int wg     = tid >> 7;          // warpgroup: K-half
    const int wg_tid = tid & 127;         // row within tile
    const int v0     = blockIdx.x * TILE_V;

    const uint32_t rawBase = smem_u32(dynsmem);
    const uint32_t bAddr   = (rawBase + 1023u) & ~1023u;   // B tiles, 1024-aligned
    uint32_t* sB = dynsmem + ((bAddr - rawBase) >> 2);
    (void)sB;

    const uint32_t mbarM0 = smem_u32(&sMbarMMA[0]);
    const uint32_t mbarM1 = smem_u32(&sMbarMMA[1]);
    const uint32_t mbarT0 = smem_u32(&sMbarTMA[0]);
    const uint32_t mbarT1 = smem_u32(&sMbarTMA[1]);
    if (tid == 0) {
        asm volatile("mbarrier.init.shared.b64 [%0], 1;" :: "r"(mbarM0) : "memory");
        asm volatile("mbarrier.init.shared.b64 [%0], 1;" :: "r"(mbarM1) : "memory");
        asm volatile("mbarrier.init.shared.b64 [%0], 1;" :: "r"(mbarT0) : "memory");
        asm volatile("mbarrier.init.shared.b64 [%0], 1;" :: "r"(mbarT1) : "memory");
    }
    if (tid < COUT) sBias[tid] = bias[tid];
    if (tid < TILE_V) {
        int v = v0 + tid;
        int z, y, x;
        if (v < n) {
            z = coors[4 * v + 1];
            y = coors[4 * v + 2];
            x = coors[4 * v + 3];
        } else {
            z = -1000; y = -1000; x = -1000;
        }
        sZ[tid] = z; sY[tid] = y; sX[tid] = x;
        int nz = z - 1, ny = y - 1, nx = x - 1;   // k=0 lookup (dz=dy=dx=-1)
        int idx = -1;
        if ((unsigned)nz < GD && (unsigned)ny < GH && (unsigned)nx < GW)
            idx = g_grid[(nz * GH + ny) * GW + nx];
        sIdx[1][tid] = idx;   // prologue buffer for k=0
    }
    if (tid < 32) {
        uint32_t a = smem_u32(&sTmem);
        asm volatile("tcgen05.alloc.cta_group::1.sync.aligned.shared::cta.b32 [%0], %1;"
                     :: "r"(a), "r"(128u) : "memory");
        asm volatile("tcgen05.relinquish_alloc_permit.cta_group::1.sync.aligned;");
    }
    __syncthreads();

    const uint32_t tmem = sTmem;
    const uint32_t warpOff = (uint32_t)(wg_tid >> 5) << 21;   // subpartition select
    const uint32_t tmemD = tmem + 64;
    int phM0 = 0, phM1 = 0;
    int phT0 = 0, phT1 = 0;

    // Preload gather registers for k=0: thread owns row wg_tid, K-half wg.
    // 2 x uint4 = 8 words = 8 TMEM cols worth (16 fp16 K-values).
    uint4 rv[2];
    {
        int idx = sIdx[1][wg_tid];
        rv[0] = make_uint4(0u, 0u, 0u, 0u);
        rv[1] = make_uint4(0u, 0u, 0u, 0u);
        if (idx >= 0) {
            const uint4* src = reinterpret_cast<const uint4*>(g_packF) + idx * 4 + wg * 2;
            rv[0] = src[0];
            rv[1] = src[1];
        }
    }
    int rIdx = -1;
    if (tid < TILE_V) {   // lookup for k=1: dz=-1, dy=-1, dx=0
        int z = sZ[tid] - 1, y = sY[tid] - 1, x = sX[tid];
        if ((unsigned)z < GD && (unsigned)y < GH && (unsigned)x < GW)
            rIdx = g_grid[(z * GH + y) * GW + x];
    }

    for (int k = 0; k < NK; k++) {
        const int st = k & 1;
        const uint32_t aT  = tmem + (st ? 16u : 0u);   // TMEM A stage (cols)
        const uint32_t bSm = bAddr + (st ? 8192u : 0u);

        // Stage reuse guard: MMA(k-2) done before overwriting A(st)/B(st).
        if (k >= 2) {
            if (st == 0) { MBARRIER_WAIT_PARITY(mbarM0, phM0 & 1); phM0++; }
            else         { MBARRIER_WAIT_PARITY(mbarM1, phM1 & 1); phM1++; }
        }

        // Kick B(k) via TMA bulk copy (8KB, async, LSU-free).
        if (tid == 0) {
            const uint32_t mbT = st == 0 ? mbarT0 : mbarT1;
            asm volatile(
                "mbarrier.arrive.expect_tx.shared.b64 _, [%0], %1;"
                :: "r"(mbT), "r"(8192u) : "memory");
            asm volatile(
                "cp.async.bulk.shared::cta.global.mbarrier::complete_tx::bytes "
                "[%0], [%1], %2, [%3];"
                :: "r"(bSm), "l"((const void*)(g_Bw + k * 4096)), "r"(8192u), "r"(mbT)
                : "memory");
        }

        // Drain staged registers into TMEM A(st): warp-collective x8 store.
        // Row = lane (within subpartition), cols = wg*8 .. wg*8+7.
        asm volatile(
            "tcgen05.st.sync.aligned.32x32b.x8.b32 [%0], "
            "{%1, %2, %3, %4, %5, %6, %7, %8};"
            :: "r"(aT + (uint32_t)(wg * 8) + warpOff),
               "r"(rv[0].x), "r"(rv[0].y), "r"(rv[0].z), "r"(rv[0].w),
               "r"(rv[1].x), "r"(rv[1].y), "r"(rv[1].z), "r"(rv[1].w)
            : "memory");
        asm volatile("tcgen05.wait::st.sync.aligned;" ::: "memory");

        // Drain staged lookup register for k+1 into sIdx[st].
        if (k + 1 < NK && tid < TILE_V)
            sIdx[st][tid] = rIdx;

        asm volatile("tcgen05.fence::before_thread_sync;" ::: "memory");
        __syncthreads();

        // Issue gather LDGs for k+1 (reads sIdx[st], just published).
        if (k + 1 < NK) {
            int idx = sIdx[st][wg_tid];
            rv[0] = make_uint4(0u, 0u, 0u, 0u);
            rv[1] = make_uint4(0u, 0u, 0u, 0u);
            if (idx >= 0) {
                const uint4* src = reinterpret_cast<const uint4*>(g_packF) + idx * 4 + wg * 2;
                rv[0] = src[0];
                rv[1] = src[1];
            }
        }

        // Issue lookup LDG for k+2 into rIdx (lands during step k+1 body).
        if (k + 2 < NK && tid < TILE_V) {
            const int kn = k + 2;
            const int dz = kn / 9 - 1, dy = (kn / 3) % 3 - 1, dx = kn % 3 - 1;
            int z = sZ[tid] + dz, y = sY[tid] + dy, x = sX[tid] + dx;
            int idx = -1;
            if ((unsigned)z < GD && (unsigned)y < GH && (unsigned)x < GW)
                idx = g_grid[(z * GH + y) * GW + x];
            rIdx = idx;
        }

        if (tid == 0) {
            if (st == 0) { MBARRIER_WAIT_PARITY(mbarT0, phT0 & 1); phT0++; }
            else         { MBARRIER_WAIT_PARITY(mbarT1, phT1 & 1); phT1++; }

            asm volatile("tcgen05.fence::after_thread_sync;" ::: "memory");
            const uint64_t bD = make_desc(bSm);
            // K=32 -> 2 TS MMAs of K=16 (A: +8 TMEM cols, B desc: +32B = +2 units).
            mma_f16_ts(tmemD, aT,     bD,     (k == 0) ? 0u : 1u);
            mma_f16_ts(tmemD, aT + 8, bD + 2, 1u);
            asm volatile(
                "tcgen05.commit.cta_group::1.mbarrier::arrive::one.shared::cluster.b64 [%0];"
                :: "r"(st == 0 ? mbarM0 : mbarM1) : "memory");
        }
    }

    MBARRIER_WAIT_PARITY(mbarM1, phM1 & 1);
    MBARRIER_WAIT_PARITY(mbarM0, phM0 & 1);
    asm volatile("tcgen05.fence::after_thread_sync;" ::: "memory");

    // Epilogue: warpgroup 0 reads D (tmem+64 .. +127); rows = voxels.
    if (tid < 128) {
        uint32_t r[64];
        asm volatile(
            "tcgen05.ld.sync.aligned.32x32b.x32.b32 "
            "{%0,%1,%2,%3,%4,%5,%6,%7,%8,%9,%10,%11,%12,%13,%14,%15,"
            "%16,%17,%18,%19,%20,%21,%22,%23,%24,%25,%26,%27,%28,%29,%30,%31}, [%32];"
            : "=r"(r[0]),"=r"(r[1]),"=r"(r[2]),"=r"(r[3]),"=r"(r[4]),"=r"(r[5]),"=r"(r[6]),"=r"(r[7]),
              "=r"(r[8]),"=r"(r[9]),"=r"(r[10]),"=r"(r[11]),"=r"(r[12]),"=r"(r[13]),"=r"(r[14]),"=r"(r[15]),
              "=r"(r[16]),"=r"(r[17]),"=r"(r[18]),"=r"(r[19]),"=r"(r[20]),"=r"(r[21]),"=r"(r[22]),"=r"(r[23]),
              "=r"(r[24]),"=r"(r[25]),"=r"(r[26]),"=r"(r[27]),"=r"(r[28]),"=r"(r[29]),"=r"(r[30]),"=r"(r[31])
            : "r"(tmemD));
        asm volatile(
            "tcgen05.ld.sync.aligned.32x32b.x32.b32 "
            "{%0,%1,%2,%3,%4,%5,%6,%7,%8,%9,%10,%11,%12,%13,%14,%15,"
            "%16,%17,%18,%19,%20,%21,%22,%23,%24,%25,%26,%27,%28,%29,%30,%31}, [%32];"
            : "=r"(r[32]),"=r"(r[33]),"=r"(r[34]),"=r"(r[35]),"=r"(r[36]),"=r"(r[37]),"=r"(r[38]),"=r"(r[39]),
              "=r"(r[40]),"=r"(r[41]),"=r"(r[42]),"=r"(r[43]),"=r"(r[44]),"=r"(r[45]),"=r"(r[46]),"=r"(r[47]),
              "=r"(r[48]),"=r"(r[49]),"=r"(r[50]),"=r"(r[51]),"=r"(r[52]),"=r"(r[53]),"=r"(r[54]),"=r"(r[55]),
              "=r"(r[56]),"=r"(r[57]),"=r"(r[58]),"=r"(r[59]),"=r"(r[60]),"=r"(r[61]),"=r"(r[62]),"=r"(r[63])
            : "r"(tmemD + 32));
        asm volatile("tcgen05.wait::ld.sync.aligned;" ::: "memory");

        int v = v0 + tid;
        if (v < n) {
            float4* op = reinterpret_cast<float4*>(out + (size_t)v * COUT);
            #pragma unroll
            for (int j = 0; j < 16; j++) {
                float4 o;
                o.x = __uint_as_float(r[4 * j + 0]) + sBias[4 * j + 0];
                o.y = __uint_as_float(r[4 * j + 1]) + sBias[4 * j + 1];
                o.z = __uint_as_float(r[4 * j + 2]) + sBias[4 * j + 2];
                o.w = __uint_as_float(r[4 * j + 3]) + sBias[4 * j + 3];
                op[j] = o;
            }
        }
    }

    __syncthreads();
    if (tid == 0) {
        asm volatile("mbarrier.inval.shared.b64 [%0];" :: "r"(mbarM0) : "memory");
        asm volatile("mbarrier.inval.shared.b64 [%0];" :: "r"(mbarM1) : "memory");
        asm volatile("mbarrier.inval.shared.b64 [%0];" :: "r"(mbarT0) : "memory");
        asm volatile("mbarrier.inval.shared.b64 [%0];" :: "r"(mbarT1) : "memory");
    }
    if (tid < 32) {
        asm volatile("tcgen05.dealloc.cta_group::1.sync.aligned.b32 %0, %1;" :: "r"(tmem), "r"(128u));
    }
#endif  // HAS_TCGEN05
}

extern "C" void kernel_launch(void* const* d_in, const int* in_sizes, int n_in,
                              void* d_out, int out_size) {
    const float* feat   = (const float*)d_in[0];
    const int*   coors  = (const int*)d_in[1];
    const float* weight = (const float*)d_in[2];
    const float* bias   = (const float*)d_in[3];
    float* out = (float*)d_out;
    const int n = in_sizes[0] / CIN;

    const int DYN_SMEM = 16384 + 1024;   // B 2x8KB + alignment slack
    cudaFuncSetAttribute(conv_tc_kernel, cudaFuncAttributeMaxDynamicSharedMemorySize, DYN_SMEM);

    init_grid_kernel<<<(GD * GH * GW / 4 + 255) / 256, 256>>>();
    const int prep_threads = n * CIN + n + NK * COUT * CIN;
    prep_kernel<<<(prep_threads + 255) / 256, 256>>>(coors, feat, weight, n);
    conv_tc_kernel<<<(n + TILE_V - 1) / TILE_V, 256, DYN_SMEM>>>(coors, bias, out, n);
}

// round 16
// speedup vs baseline: 1.4203x; 1.4203x over previous
#include <cuda_runtime.h>
#include <cuda_fp16.h>
#include <cstdint>

#define GD 160
#define GH 160
#define GW 160
#define CIN 32
#define COUT 64
#define NK 27
#define NSTAGE 14            // ceil(27/2) fused K=64 stages
#define TILE_V 128
#define NMAX 400000

#if defined(__CUDA_ARCH_FEAT_SM103_ALL) || defined(__CUDA_ARCH_FEAT_SM100_ALL) || defined(__CUDA_ARCH_FEAT_SM101_ALL)
#define HAS_TCGEN05 1
#else
#define HAS_TCGEN05 0
#endif

// ---------------- device scratch ----------------
__device__ int      g_grid[GD * GH * GW];        // voxel -> row index
__device__ __half   g_packF[NMAX * CIN];         // fp16 features (64B per voxel row)
__device__ __half   g_Bw[NSTAGE * 4096];         // 14 x 8KB fused pre-swizzled B tiles
                                                 // (zero-init covers k=27 pad)

// ---------------- helpers ----------------
__device__ __forceinline__ uint32_t smem_u32(const void* p) {
    uint32_t a;
    asm("{ .reg .u64 t; cvta.to.shared.u64 t, %1; cvt.u32.u64 %0, t; }" : "=r"(a) : "l"(p));
    return a;
}

__host__ __device__ __forceinline__ uint32_t swz128(uint32_t off) {
    return off ^ ((off >> 3) & 0x70);
}

// SMEM descriptor: SW128, version=1, SBO=64 (1024B), LBO=1 (16B)
__device__ __forceinline__ uint64_t make_desc(uint32_t addr) {
    const uint64_t base =
        (uint64_t(2) << 61) | (uint64_t(1) << 46) | (uint64_t(64) << 32) | (uint64_t(1) << 16);
    return base | ((uint64_t)(addr >> 4) & 0x3FFF);
}

// idesc kind::f16: accum F32 (bit4), A=F16, B=F16, N=64 (8<<17), M=128 (8<<24)
#define MMA_IDESC 0x8100010u

#if HAS_TCGEN05
__device__ __forceinline__ void mma_f16_ss(uint32_t d_tmem, uint64_t a_desc,
                                           uint64_t b_desc, uint32_t en) {
    asm volatile(
        "{\n\t"
        ".reg .pred p;\n\t"
        "setp.ne.u32 p, %5, 0;\n\t"
        "tcgen05.mma.cta_group::1.kind::f16 [%0], %1, %2, %3, {%4, %4, %4, %4}, p;\n\t"
        "}"
        :: "r"(d_tmem), "l"(a_desc), "l"(b_desc), "r"(MMA_IDESC), "r"(0u), "r"(en)
        : "memory");
}
#endif

#define MBARRIER_WAIT_PARITY(mbar, parity) do {                                   \
    uint32_t _m = (mbar); uint32_t _p = (parity); uint32_t _done;                  \
    asm volatile(                                                                  \
        "{\n\t.reg .pred p;\n\t"                                                   \
        "mbarrier.try_wait.parity.acquire.cta.shared::cta.b64 p, [%1], %2;\n\t"    \
        "selp.b32 %0, 1, 0, p;\n\t}"                                               \
        : "=r"(_done) : "r"(_m), "r"(_p) : "memory");                              \
    if (!_done) {                                                                  \
        asm volatile(                                                              \
            "{\n\t.reg .pred P1;\n\t"                                              \
            "WL_%=:\n\t"                                                           \
            "mbarrier.try_wait.parity.acquire.cta.shared::cta.b64 P1, [%0], %1, 0x989680;\n\t" \
            "@P1 bra.uni WD_%=;\n\t"                                               \
            "bra.uni WL_%=;\n\t"                                                   \
            "WD_%=:\n\t}"                                                          \
            :: "r"(_m), "r"(_p) : "memory");                                       \
    }                                                                              \
} while (0)

// ---------------- prep kernels ----------------
__global__ void init_grid_kernel() {
    int i = blockIdx.x * blockDim.x + threadIdx.x;
    int4* p = reinterpret_cast<int4*>(g_grid);
    const int total = (GD * GH * GW) / 4;
    if (i < total) p[i] = make_int4(-1, -1, -1, -1);
}

// Fused: pack features (fp16) + scatter + pack weights (fp16, fused k-pairs).
__global__ void prep_kernel(const int* __restrict__ coors,
                            const float* __restrict__ feat,
                            const float* __restrict__ weight,
                            int n) {
    int i = blockIdx.x * blockDim.x + threadIdx.x;
    const int nF = n * CIN;
    if (i < nF) {
        g_packF[i] = __float2half(feat[i]);
        return;
    }
    i -= nF;
    if (i < n) {
        int z = coors[4 * i + 1];
        int y = coors[4 * i + 2];
        int x = coors[4 * i + 3];
        g_grid[(z * GH + y) * GW + x] = i;
        return;
    }
    i -= n;
    if (i < NK * COUT * CIN) {
        int k  = i / (COUT * CIN);
        int rr = i % (COUT * CIN);
        int nn = rr / CIN;   // cout (B row)
        int c  = rr % CIN;   // cin
        float w = weight[k * CIN * COUT + c * COUT + nn];
        // Fused tile j = k/2; k-half h = k&1 occupies bytes h*64..h*64+63 of row nn.
        int j = k >> 1, h = k & 1;
        uint32_t sw = swz128((uint32_t)(nn * 128 + h * 64 + c * 2));
        g_Bw[j * 4096 + (sw >> 1)] = __float2half(w);
    }
}

// ---------------- main tensor-core kernel ----------------
// K=64 fused stages (14 instead of 27 barriers/commits). A row = 128B:
// quads 0-3 = k_even features, 4-7 = k_odd. B fused tile = 8KB fully used.
// Register-staged gather (distance 1) + register-staged lookups (distance 2,
// thread tid covers (voxel tid&127, khalf tid>>7)). 4 MMAs (K=16) per stage.
// Dyn smem: A0[16K] A1[16K] B0[8K] B1[8K] = 48KB -> 4 CTAs/SM.
__global__ __launch_bounds__(256) void conv_tc_kernel(
    const int*   __restrict__ coors,
    const float* __restrict__ bias,
    float*       __restrict__ out,
    int n)
{
#if HAS_TCGEN05
    extern __shared__ uint32_t dynsmem[];
    __shared__ int   sIdx[2][2][TILE_V];   // [stage-buf][khalf][voxel]
    __shared__ int   sZ[TILE_V], sY[TILE_V], sX[TILE_V];
    __shared__ float sBias[COUT];
    __shared__ uint32_t sTmem;
    __shared__ __align__(8) uint64_t sMbarMMA[2];
    __shared__ __align__(8) uint64_t sMbarTMA[2];

    const int tid   = threadIdx.x;
    const int lkV   = tid & 127;     // voxel this thread looks up
    const int lkH   = tid >> 7;      // khalf this thread looks up
    const int v0    = blockIdx.x * TILE_V;

    const uint32_t rawBase = smem_u32(dynsmem);
    const uint32_t aAddr   = (rawBase + 1023u) & ~1023u;
    uint32_t* sT = dynsmem + ((aAddr - rawBase) >> 2);

    const uint32_t mbarM0 = smem_u32(&sMbarMMA[0]);
    const uint32_t mbarM1 = smem_u32(&sMbarMMA[1]);
    const uint32_t mbarT0 = smem_u32(&sMbarTMA[0]);
    const uint32_t mbarT1 = smem_u32(&sMbarTMA[1]);
    if (tid == 0) {
        asm volatile("mbarrier.init.shared.b64 [%0], 1;" :: "r"(mbarM0) : "memory");
        asm volatile("mbarrier.init.shared.b64 [%0], 1;" :: "r"(mbarM1) : "memory");
        asm volatile("mbarrier.init.shared.b64 [%0], 1;" :: "r"(mbarT0) : "memory");
        asm volatile("mbarrier.init.shared.b64 [%0], 1;" :: "r"(mbarT1) : "memory");
    }
    if (tid < COUT) sBias[tid] = bias[tid];
    if (tid < TILE_V) {
        int v = v0 + tid;
        int z, y, x;
        if (v < n) {
            z = coors[4 * v + 1];
            y = coors[4 * v + 2];
            x = coors[4 * v + 3];
        } else {
            z = -1000; y = -1000; x = -1000;
        }
        sZ[tid] = z; sY[tid] = y; sX[tid] = x;
    }
    if (tid < 32) {
        uint32_t a = smem_u32(&sTmem);
        asm volatile("tcgen05.alloc.cta_group::1.sync.aligned.shared::cta.b32 [%0], %1;"
                     :: "r"(a), "r"(64u) : "memory");
        asm volatile("tcgen05.relinquish_alloc_permit.cta_group::1.sync.aligned;");
    }
    __syncthreads();

    // Prologue lookups for stage 0 (k = lkH: k0 has d=(-1,-1,-1), k1 d=(-1,-1,0)).
    {
        const int k = lkH;
        const int dz = k / 9 - 1, dy = (k / 3) % 3 - 1, dx = k % 3 - 1;
        int z = sZ[lkV] + dz, y = sY[lkV] + dy, x = sX[lkV] + dx;
        int idx = -1;
        if ((unsigned)z < GD && (unsigned)y < GH && (unsigned)x < GW)
            idx = g_grid[(z * GH + y) * GW + x];
        sIdx[1][lkH][lkV] = idx;
    }
    __syncthreads();

    const uint32_t tmem = sTmem;
    int phM0 = 0, phM1 = 0;
    int phT0 = 0, phT1 = 0;

    // Preload gather registers for stage 0: 1024 uint4 slots (128 rows x 8 quads),
    // 4/thread. Quad q<4 = k_even (khalf 0), q>=4 = k_odd (khalf 1).
    uint4 rv[4];
    {
        #pragma unroll
        for (int ss = 0; ss < 4; ss++) {
            int slot = ss * 256 + tid;
            int v = slot >> 3;
            int q = slot & 7;
            int idx = sIdx[1][q >> 2][v];
            uint4 val = make_uint4(0u, 0u, 0u, 0u);
            if (idx >= 0)
                val = reinterpret_cast<const uint4*>(g_packF)[idx * 4 + (q & 3)];
            rv[ss] = val;
        }
    }
    // Prologue lookup for stage 1 (k = 2 + lkH) -> register.
    int rIdx = -1;
    {
        const int k = 2 + lkH;
        const int dz = k / 9 - 1, dy = (k / 3) % 3 - 1, dx = k % 3 - 1;
        int z = sZ[lkV] + dz, y = sY[lkV] + dy, x = sX[lkV] + dx;
        if ((unsigned)z < GD && (unsigned)y < GH && (unsigned)x < GW)
            rIdx = g_grid[(z * GH + y) * GW + x];
    }

    for (int s = 0; s < NSTAGE; s++) {
        const int st = s & 1;
        const uint32_t aSm = aAddr + (st ? 16384u : 0u);
        const uint32_t bSm = aAddr + 32768u + (st ? 8192u : 0u);

        // Stage reuse guard: MMA(s-2) done before overwriting A(st)/B(st).
        if (s >= 2) {
            if (st == 0) { MBARRIER_WAIT_PARITY(mbarM0, phM0 & 1); phM0++; }
            else         { MBARRIER_WAIT_PARITY(mbarM1, phM1 & 1); phM1++; }
        }

        // Kick fused B(s) via TMA bulk copy (8KB, async, LSU-free).
        if (tid == 0) {
            const uint32_t mbT = st == 0 ? mbarT0 : mbarT1;
            asm volatile(
                "mbarrier.arrive.expect_tx.shared.b64 _, [%0], %1;"
                :: "r"(mbT), "r"(8192u) : "memory");
            asm volatile(
                "cp.async.bulk.shared::cta.global.mbarrier::complete_tx::bytes "
                "[%0], [%1], %2, [%3];"
                :: "r"(bSm), "l"((const void*)(g_Bw + s * 4096)), "r"(8192u), "r"(mbT)
                : "memory");
        }

        // Drain staged gather registers into A(st): STS.128, swizzled quads.
        uint4* aDst = reinterpret_cast<uint4*>(sT + ((aSm - aAddr) >> 2));
        #pragma unroll
        for (int ss = 0; ss < 4; ss++) {
            int slot = ss * 256 + tid;
            int v = slot >> 3;
            int q = slot & 7;
            aDst[v * 8 + (q ^ (v & 7))] = rv[ss];
        }

        // Drain staged lookup register (stage s+1) into sIdx[st].
        if (s + 1 < NSTAGE)
            sIdx[st][lkH][lkV] = rIdx;

        asm volatile("fence.proxy.async.shared::cta;" ::: "memory");
        __syncthreads();

        // Issue gather LDGs for stage s+1 (reads sIdx[st], just published).
        if (s + 1 < NSTAGE) {
            #pragma unroll
            for (int ss = 0; ss < 4; ss++) {
                int slot = ss * 256 + tid;
                int v = slot >> 3;
                int q = slot & 7;
                int idx = sIdx[st][q >> 2][v];
                uint4 val = make_uint4(0u, 0u, 0u, 0u);
                if (idx >= 0)
                    val = reinterpret_cast<const uint4*>(g_packF)[idx * 4 + (q & 3)];
                rv[ss] = val;
            }
        }

        // Issue lookup LDG for stage s+2 into rIdx.
        if (s + 2 < NSTAGE) {
            const int k = 2 * (s + 2) + lkH;
            int idx = -1;
            if (k < NK) {
                const int dz = k / 9 - 1, dy = (k / 3) % 3 - 1, dx = k % 3 - 1;
                int z = sZ[lkV] + dz, y = sY[lkV] + dy, x = sX[lkV] + dx;
                if ((unsigned)z < GD && (unsigned)y < GH && (unsigned)x < GW)
                    idx = g_grid[(z * GH + y) * GW + x];
            }
            rIdx = idx;
        }

        if (tid == 0) {
            if (st == 0) { MBARRIER_WAIT_PARITY(mbarT0, phT0 & 1); phT0++; }
            else         { MBARRIER_WAIT_PARITY(mbarT1, phT1 & 1); phT1++; }

            const uint64_t aD = make_desc(aSm);
            const uint64_t bD = make_desc(bSm);
            // K=64 fused -> 4 MMAs of K=16 (desc step +2 = 32B within SW128 atom).
            mma_f16_ss(tmem, aD,     bD,     (s == 0) ? 0u : 1u);
            mma_f16_ss(tmem, aD + 2, bD + 2, 1u);
            mma_f16_ss(tmem, aD + 4, bD + 4, 1u);
            mma_f16_ss(tmem, aD + 6, bD + 6, 1u);
            asm volatile(
                "tcgen05.commit.cta_group::1.mbarrier::arrive::one.shared::cluster.b64 [%0];"
                :: "r"(st == 0 ? mbarM0 : mbarM1) : "memory");
        }
    }

    MBARRIER_WAIT_PARITY(mbarM1, phM1 & 1);
    MBARRIER_WAIT_PARITY(mbarM0, phM0 & 1);
    asm volatile("tcgen05.fence::after_thread_sync;" ::: "memory");

    // Epilogue: warpgroup 0 reads TMEM rows = voxels.
    if (tid < 128) {
        uint32_t r[64];
        asm volatile(
            "tcgen05.ld.sync.aligned.32x32b.x32.b32 "
            "{%0,%1,%2,%3,%4,%5,%6,%7,%8,%9,%10,%11,%12,%13,%14,%15,"
            "%16,%17,%18,%19,%20,%21,%22,%23,%24,%25,%26,%27,%28,%29,%30,%31}, [%32];"
            : "=r"(r[0]),"=r"(r[1]),"=r"(r[2]),"=r"(r[3]),"=r"(r[4]),"=r"(r[5]),"=r"(r[6]),"=r"(r[7]),
              "=r"(r[8]),"=r"(r[9]),"=r"(r[10]),"=r"(r[11]),"=r"(r[12]),"=r"(r[13]),"=r"(r[14]),"=r"(r[15]),
              "=r"(r[16]),"=r"(r[17]),"=r"(r[18]),"=r"(r[19]),"=r"(r[20]),"=r"(r[21]),"=r"(r[22]),"=r"(r[23]),
              "=r"(r[24]),"=r"(r[25]),"=r"(r[26]),"=r"(r[27]),"=r"(r[28]),"=r"(r[29]),"=r"(r[30]),"=r"(r[31])
            : "r"(tmem));
        asm volatile(
            "tcgen05.ld.sync.aligned.32x32b.x32.b32 "
            "{%0,%1,%2,%3,%4,%5,%6,%7,%8,%9,%10,%11,%12,%13,%14,%15,"
            "%16,%17,%18,%19,%20,%21,%22,%23,%24,%25,%26,%27,%28,%29,%30,%31}, [%32];"
            : "=r"(r[32]),"=r"(r[33]),"=r"(r[34]),"=r"(r[35]),"=r"(r[36]),"=r"(r[37]),"=r"(r[38]),"=r"(r[39]),
              "=r"(r[40]),"=r"(r[41]),"=r"(r[42]),"=r"(r[43]),"=r"(r[44]),"=r"(r[45]),"=r"(r[46]),"=r"(r[47]),
              "=r"(r[48]),"=r"(r[49]),"=r"(r[50]),"=r"(r[51]),"=r"(r[52]),"=r"(r[53]),"=r"(r[54]),"=r"(r[55]),
              "=r"(r[56]),"=r"(r[57]),"=r"(r[58]),"=r"(r[59]),"=r"(r[60]),"=r"(r[61]),"=r"(r[62]),"=r"(r[63])
            : "r"(tmem + 32));
        asm volatile("tcgen05.wait::ld.sync.aligned;" ::: "memory");

        int v = v0 + tid;
        if (v < n) {
            float4* op = reinterpret_cast<float4*>(out + (size_t)v * COUT);
            #pragma unroll
            for (int j = 0; j < 16; j++) {
                float4 o;
                o.x = __uint_as_float(r[4 * j + 0]) + sBias[4 * j + 0];
                o.y = __uint_as_float(r[4 * j + 1]) + sBias[4 * j + 1];
                o.z = __uint_as_float(r[4 * j + 2]) + sBias[4 * j + 2];
                o.w = __uint_as_float(r[4 * j + 3]) + sBias[4 * j + 3];
                op[j] = o;
            }
        }
    }

    __syncthreads();
    if (tid == 0) {
        asm volatile("mbarrier.inval.shared.b64 [%0];" :: "r"(mbarM0) : "memory");
        asm volatile("mbarrier.inval.shared.b64 [%0];" :: "r"(mbarM1) : "memory");
        asm volatile("mbarrier.inval.shared.b64 [%0];" :: "r"(mbarT0) : "memory");
        asm volatile("mbarrier.inval.shared.b64 [%0];" :: "r"(mbarT1) : "memory");
    }
    if (tid < 32) {
        asm volatile("tcgen05.dealloc.cta_group::1.sync.aligned.b32 %0, %1;" :: "r"(tmem), "r"(64u));
    }
#endif  // HAS_TCGEN05
}

extern "C" void kernel_launch(void* const* d_in, const int* in_sizes, int n_in,
                              void* d_out, int out_size) {
    const float* feat   = (const float*)d_in[0];
    const int*   coors  = (const int*)d_in[1];
    const float* weight = (const float*)d_in[2];
    const float* bias   = (const float*)d_in[3];
    float* out = (float*)d_out;
    const int n = in_sizes[0] / CIN;

    const int DYN_SMEM = 49152 + 1024;   // A 2x16KB + B 2x8KB + alignment slack
    cudaFuncSetAttribute(conv_tc_kernel, cudaFuncAttributeMaxDynamicSharedMemorySize, DYN_SMEM);

    init_grid_kernel<<<(GD * GH * GW / 4 + 255) / 256, 256>>>();
    const int prep_threads = n * CIN + n + NK * COUT * CIN;
    prep_kernel<<<(prep_threads + 255) / 256, 256>>>(coors, feat, weight, n);
    conv_tc_kernel<<<(n + TILE_V - 1) / TILE_V, 256, DYN_SMEM>>>(coors, bias, out, n);
}